// round 4
// baseline (speedup 1.0000x reference)
#include <cuda_runtime.h>
#include <math.h>
#include <stdint.h>

// Problem constants
#define D_MODEL 1024
#define NHEAD   16
#define HD      64
#define SEQ     2048
#define BATCH   2
#define NTOK    (BATCH * SEQ)          // 4096
#define QKV_LD  (3 * D_MODEL)          // 3072

// HBM scratch (no cudaMalloc allowed)
__device__ float g_qkv[(size_t)NTOK * QKV_LD];       // [4096, 3072]
__device__ float g_att[(size_t)NTOK * D_MODEL];      // [4096, 1024]
__device__ float g_wqkvF[(size_t)D_MODEL * QKV_LD];  // fragment-ordered Wqkv (tf32)
__device__ float g_woutF[(size_t)D_MODEL * D_MODEL]; // fragment-ordered Wout (tf32)

// ---------------------------------------------------------------------------
__device__ __forceinline__ unsigned f2tf(float f) {
    unsigned u;
    asm("cvt.rna.tf32.f32 %0, %1;" : "=r"(u) : "f"(f));
    return u;
}
__device__ __forceinline__ float f2tf_f(float f) { return __uint_as_float(f2tf(f)); }

__device__ __forceinline__ void mma_tf32(float c[4], const unsigned a[4],
                                         unsigned b0, unsigned b1) {
    asm volatile(
        "mma.sync.aligned.m16n8k8.row.col.f32.tf32.tf32.f32 "
        "{%0,%1,%2,%3}, {%4,%5,%6,%7}, {%8,%9}, {%0,%1,%2,%3};"
        : "+f"(c[0]), "+f"(c[1]), "+f"(c[2]), "+f"(c[3])
        : "r"(a[0]), "r"(a[1]), "r"(a[2]), "r"(a[3]), "r"(b0), "r"(b1));
}

// ---------------------------------------------------------------------------
// Weight permute: W[K][N] row-major fp32  ->  Wf fragment order (tf32 floats)
// Layout: [ncol = n/64][ks = k/8][nb 0..7][lane 0..31] float2
//   lane: r4 = lane>>2, c4 = lane&3
//   float2 = { W[ks*8 + c4][ncol*64 + nb*8 + r4], W[ks*8 + c4 + 4][same n] }
// ---------------------------------------------------------------------------
__global__ __launch_bounds__(256) void permute_w_kernel(
    const float* __restrict__ W, float* __restrict__ Wf, int K, int N)
{
    const int idx = blockIdx.x * 256 + threadIdx.x;
    const int total = (N / 64) * (K / 8) * 8 * 32;
    if (idx >= total) return;
    const int lane = idx & 31;
    const int nb   = (idx >> 5) & 7;
    const int tmp  = idx >> 8;
    const int per  = K / 8;
    const int ks   = tmp % per;
    const int ncol = tmp / per;
    const int n = ncol * 64 + nb * 8 + (lane >> 2);
    const int k = ks * 8 + (lane & 3);
    Wf[(size_t)idx * 2]     = f2tf_f(W[(size_t)k * N + n]);
    Wf[(size_t)idx * 2 + 1] = f2tf_f(W[(size_t)(k + 4) * N + n]);
}

// ---------------------------------------------------------------------------
// TF32 mma.sync GEMM v2: C[M,N] = A[M,K] @ W[K,N] + bias[N]
// B-fragments streamed from gmem (L2-resident, pre-permuted).
// A staged in fragment-major smem: Af[ks(2)][c4(4)][mb(8)][r4(8)] float4,
// c4-stride padded to 264 floats (1056 B) -> conflict-free LDS.128.
// CTA 128x128, 4 warps (2x2 of 64x64 warp tiles), 2 CTAs/SM.
// ---------------------------------------------------------------------------
#define AF_KS_STR 1056   // floats per ks (4 * 264)
#define AF_BUF    2112   // floats per buffer

__global__ __launch_bounds__(128, 2) void gemm_v2_kernel(
    const float* __restrict__ A, const float* __restrict__ Wf,
    const float* __restrict__ bias, float* __restrict__ C,
    int M, int N, int K)
{
    __shared__ float As[2][AF_BUF];

    const int tid  = threadIdx.x;
    const int lane = tid & 31;
    const int warp = tid >> 5;
    const int r4 = lane >> 2;
    const int c4 = lane & 3;
    const int wrow = warp >> 1;     // 0..1
    const int wcol = warp & 1;      // 0..1
    const int row0 = blockIdx.y * 128;
    const int col0 = blockIdx.x * 128;

    // staging thread mapping
    const int sr4 = tid & 7;
    const int smb = (tid >> 3) & 7;
    const int sks = tid >> 6;       // 0..1
    const float* Abase = A + (size_t)(row0 + smb * 16 + sr4) * K + sks * 8;

    // B fragment base for this warp (ncol = col0/64 + wcol)
    const int per = K / 8;
    const float* Bbase = Wf + ((size_t)(blockIdx.x * 2 + wcol) * per) * 512 + lane * 2;

    float acc[4][8][4];
#pragma unroll
    for (int mf = 0; mf < 4; mf++)
#pragma unroll
        for (int nf = 0; nf < 8; nf++)
#pragma unroll
            for (int x = 0; x < 4; x++) acc[mf][nf][x] = 0.f;

    float2 bf[2][2][8];
    float4 sv0, sv1, sv2, sv3;

    const int nchunk = K / 16;

    // prologue
    {
        sv0 = *(const float4*)(Abase);
        sv1 = *(const float4*)(Abase + 4);
        sv2 = *(const float4*)(Abase + (size_t)8 * K);
        sv3 = *(const float4*)(Abase + (size_t)8 * K + 4);
        float* d = As[0] + sks * AF_KS_STR + smb * 32 + sr4 * 4;
        *(float4*)(d + 0 * 264) = make_float4(f2tf_f(sv0.x), f2tf_f(sv2.x), f2tf_f(sv1.x), f2tf_f(sv3.x));
        *(float4*)(d + 1 * 264) = make_float4(f2tf_f(sv0.y), f2tf_f(sv2.y), f2tf_f(sv1.y), f2tf_f(sv3.y));
        *(float4*)(d + 2 * 264) = make_float4(f2tf_f(sv0.z), f2tf_f(sv2.z), f2tf_f(sv1.z), f2tf_f(sv3.z));
        *(float4*)(d + 3 * 264) = make_float4(f2tf_f(sv0.w), f2tf_f(sv2.w), f2tf_f(sv1.w), f2tf_f(sv3.w));
#pragma unroll
        for (int ks = 0; ks < 2; ks++)
#pragma unroll
            for (int nf = 0; nf < 8; nf++)
                bf[0][ks][nf] = *(const float2*)(Bbase + (size_t)ks * 512 + nf * 64);
    }
    __syncthreads();

    for (int c = 0; c < nchunk; c++) {
        const int pp = c & 1;
        const bool nx = (c + 1) < nchunk;
        if (nx) {
            const int k0 = (c + 1) * 16;
            sv0 = *(const float4*)(Abase + k0);
            sv1 = *(const float4*)(Abase + k0 + 4);
            sv2 = *(const float4*)(Abase + (size_t)8 * K + k0);
            sv3 = *(const float4*)(Abase + (size_t)8 * K + k0 + 4);
#pragma unroll
            for (int ks = 0; ks < 2; ks++)
#pragma unroll
                for (int nf = 0; nf < 8; nf++)
                    bf[pp ^ 1][ks][nf] =
                        *(const float2*)(Bbase + ((size_t)(c + 1) * 2 + ks) * 512 + nf * 64);
        }

        // compute chunk c
#pragma unroll
        for (int ks = 0; ks < 2; ks++) {
            float4 af[4];
            const float* ab = As[pp] + ks * AF_KS_STR + c4 * 264 + wrow * 128 + r4 * 4;
#pragma unroll
            for (int mf = 0; mf < 4; mf++) af[mf] = *(const float4*)(ab + mf * 32);
#pragma unroll
            for (int nf = 0; nf < 8; nf++) {
                const unsigned b0 = __float_as_uint(bf[pp][ks][nf].x);
                const unsigned b1 = __float_as_uint(bf[pp][ks][nf].y);
#pragma unroll
                for (int mf = 0; mf < 4; mf++)
                    mma_tf32(acc[mf][nf], (const unsigned*)&af[mf], b0, b1);
            }
        }

        if (nx) {
            float* d = As[pp ^ 1] + sks * AF_KS_STR + smb * 32 + sr4 * 4;
            *(float4*)(d + 0 * 264) = make_float4(f2tf_f(sv0.x), f2tf_f(sv2.x), f2tf_f(sv1.x), f2tf_f(sv3.x));
            *(float4*)(d + 1 * 264) = make_float4(f2tf_f(sv0.y), f2tf_f(sv2.y), f2tf_f(sv1.y), f2tf_f(sv3.y));
            *(float4*)(d + 2 * 264) = make_float4(f2tf_f(sv0.z), f2tf_f(sv2.z), f2tf_f(sv1.z), f2tf_f(sv3.z));
            *(float4*)(d + 3 * 264) = make_float4(f2tf_f(sv0.w), f2tf_f(sv2.w), f2tf_f(sv1.w), f2tf_f(sv3.w));
        }
        __syncthreads();
    }

    // epilogue
#pragma unroll
    for (int mf = 0; mf < 4; mf++) {
        const int r = row0 + wrow * 64 + mf * 16 + r4;
#pragma unroll
        for (int nf = 0; nf < 8; nf++) {
            const int cc = col0 + wcol * 64 + nf * 8 + 2 * c4;
            const float bx = bias[cc], by = bias[cc + 1];
            *(float2*)&C[(size_t)r * N + cc] =
                make_float2(acc[mf][nf][0] + bx, acc[mf][nf][1] + by);
            *(float2*)&C[(size_t)(r + 8) * N + cc] =
                make_float2(acc[mf][nf][2] + bx, acc[mf][nf][3] + by);
        }
    }
}

// ---------------------------------------------------------------------------
// FlashAttention tf32 mma, v2: 8 warps x 32 queries = 256 q / CTA.
// Each warp: 2 m-frags (K/V fragments reused for both -> half LDS per mma).
// 32-key tiles. Online softmax. P staged per-warp (stride 36).
// ---------------------------------------------------------------------------
#define AKSTR 68
#define AVSTR 72
#define APSTR 36
#define AOFF_K 0
#define AOFF_V (32 * AKSTR)                    // 2176
#define AOFF_P (AOFF_V + 32 * AVSTR)           // 4480
#define ATT_SMEM_BYTES (256 * 68 * 4)          // 69632 (Q-staging dominates)

__global__ __launch_bounds__(256, 1) void attn_mma_v2_kernel()
{
    extern __shared__ float sm[];
    const int tid  = threadIdx.x;
    const int lane = tid & 31;
    const int warp = tid >> 5;
    const int b  = blockIdx.z;
    const int h  = blockIdx.y;
    const int q0 = blockIdx.x * 256;
    const int r4 = lane >> 2;
    const int c4 = lane & 3;

    float* Ps = sm + AOFF_P + warp * (32 * APSTR);

    // ---- Stage Q (scaled, tf32) into sm[256][68], grab frags ----
    {
        const float* qb = g_qkv + ((size_t)b * SEQ + q0) * QKV_LD + h * (3 * HD);
        for (int i = tid; i < 256 * 16; i += 256) {
            const int r = i >> 4;
            const int cc = (i & 15) * 4;
            float4 v = *(const float4*)(qb + (size_t)r * QKV_LD + cc);
            sm[r * AKSTR + cc + 0] = f2tf_f(v.x * 0.125f);
            sm[r * AKSTR + cc + 1] = f2tf_f(v.y * 0.125f);
            sm[r * AKSTR + cc + 2] = f2tf_f(v.z * 0.125f);
            sm[r * AKSTR + cc + 3] = f2tf_f(v.w * 0.125f);
        }
    }
    __syncthreads();

    unsigned qf[2][8][4];
#pragma unroll
    for (int mf = 0; mf < 2; mf++) {
        const int m = warp * 32 + mf * 16 + r4;
#pragma unroll
        for (int kk = 0; kk < 8; kk++) {
            const int k = kk * 8 + c4;
            qf[mf][kk][0] = __float_as_uint(sm[m * AKSTR + k]);
            qf[mf][kk][1] = __float_as_uint(sm[(m + 8) * AKSTR + k]);
            qf[mf][kk][2] = __float_as_uint(sm[m * AKSTR + k + 4]);
            qf[mf][kk][3] = __float_as_uint(sm[(m + 8) * AKSTR + k + 4]);
        }
    }
    __syncthreads();

    float oacc[2][8][4];
#pragma unroll
    for (int mf = 0; mf < 2; mf++)
#pragma unroll
        for (int j = 0; j < 8; j++)
#pragma unroll
            for (int x = 0; x < 4; x++) oacc[mf][j][x] = 0.f;
    float mrow[2][2] = {{-INFINITY, -INFINITY}, {-INFINITY, -INFINITY}};
    float lrow[2][2] = {{0.f, 0.f}, {0.f, 0.f}};

    for (int s0 = 0; s0 < SEQ; s0 += 32) {
        // ---- stage K,V tiles (32 keys, tf32) ----
        const float* kvb = g_qkv + ((size_t)b * SEQ + s0) * QKV_LD + h * (3 * HD) + HD;
        for (int i = tid; i < 32 * 16; i += 256) {
            const int r = i >> 4;
            const int cc = (i & 15) * 4;
            const float* rp = kvb + (size_t)r * QKV_LD;
            float4 kv = *(const float4*)(rp + cc);
            float4 vv = *(const float4*)(rp + HD + cc);
            sm[AOFF_K + r * AKSTR + cc + 0] = f2tf_f(kv.x);
            sm[AOFF_K + r * AKSTR + cc + 1] = f2tf_f(kv.y);
            sm[AOFF_K + r * AKSTR + cc + 2] = f2tf_f(kv.z);
            sm[AOFF_K + r * AKSTR + cc + 3] = f2tf_f(kv.w);
            sm[AOFF_V + r * AVSTR + cc + 0] = f2tf_f(vv.x);
            sm[AOFF_V + r * AVSTR + cc + 1] = f2tf_f(vv.y);
            sm[AOFF_V + r * AVSTR + cc + 2] = f2tf_f(vv.z);
            sm[AOFF_V + r * AVSTR + cc + 3] = f2tf_f(vv.w);
        }
        __syncthreads();

        // ---- S = Q @ K^T (K-frags reused across both m-frags) ----
        float sacc[2][4][4];
#pragma unroll
        for (int mf = 0; mf < 2; mf++)
#pragma unroll
            for (int j = 0; j < 4; j++)
#pragma unroll
                for (int x = 0; x < 4; x++) sacc[mf][j][x] = 0.f;
#pragma unroll
        for (int j = 0; j < 4; j++) {
#pragma unroll
            for (int kk = 0; kk < 8; kk++) {
                const int key = j * 8 + r4;
                const int d = kk * 8 + c4;
                const unsigned b0 = __float_as_uint(sm[AOFF_K + key * AKSTR + d]);
                const unsigned b1 = __float_as_uint(sm[AOFF_K + key * AKSTR + d + 4]);
                mma_tf32(sacc[0][j], qf[0][kk], b0, b1);
                mma_tf32(sacc[1][j], qf[1][kk], b0, b1);
            }
        }

        // ---- online softmax per m-frag ----
#pragma unroll
        for (int mf = 0; mf < 2; mf++) {
            float mA = sacc[mf][0][0], mB = sacc[mf][0][2];
#pragma unroll
            for (int j = 0; j < 4; j++) {
                mA = fmaxf(mA, fmaxf(sacc[mf][j][0], sacc[mf][j][1]));
                mB = fmaxf(mB, fmaxf(sacc[mf][j][2], sacc[mf][j][3]));
            }
            mA = fmaxf(mA, __shfl_xor_sync(0xffffffffu, mA, 1));
            mA = fmaxf(mA, __shfl_xor_sync(0xffffffffu, mA, 2));
            mB = fmaxf(mB, __shfl_xor_sync(0xffffffffu, mB, 1));
            mB = fmaxf(mB, __shfl_xor_sync(0xffffffffu, mB, 2));
            const float mnA = fmaxf(mrow[mf][0], mA);
            const float mnB = fmaxf(mrow[mf][1], mB);
            const float alA = __expf(mrow[mf][0] - mnA);
            const float alB = __expf(mrow[mf][1] - mnB);
            mrow[mf][0] = mnA; mrow[mf][1] = mnB;

            float sumA = 0.f, sumB = 0.f;
#pragma unroll
            for (int j = 0; j < 4; j++) {
                const float p0 = __expf(sacc[mf][j][0] - mnA);
                const float p1 = __expf(sacc[mf][j][1] - mnA);
                const float p2 = __expf(sacc[mf][j][2] - mnB);
                const float p3 = __expf(sacc[mf][j][3] - mnB);
                sumA += p0 + p1;
                sumB += p2 + p3;
                const int cc = j * 8 + 2 * c4;
                const int rA = mf * 16 + r4;
                Ps[rA * APSTR + cc]           = f2tf_f(p0);
                Ps[rA * APSTR + cc + 1]       = f2tf_f(p1);
                Ps[(rA + 8) * APSTR + cc]     = f2tf_f(p2);
                Ps[(rA + 8) * APSTR + cc + 1] = f2tf_f(p3);
            }
            sumA += __shfl_xor_sync(0xffffffffu, sumA, 1);
            sumA += __shfl_xor_sync(0xffffffffu, sumA, 2);
            sumB += __shfl_xor_sync(0xffffffffu, sumB, 1);
            sumB += __shfl_xor_sync(0xffffffffu, sumB, 2);
            lrow[mf][0] = lrow[mf][0] * alA + sumA;
            lrow[mf][1] = lrow[mf][1] * alB + sumB;
#pragma unroll
            for (int j = 0; j < 8; j++) {
                oacc[mf][j][0] *= alA; oacc[mf][j][1] *= alA;
                oacc[mf][j][2] *= alB; oacc[mf][j][3] *= alB;
            }
        }
        __syncwarp();

        // ---- O += P @ V (V-frags reused across both m-frags) ----
#pragma unroll
        for (int kk = 0; kk < 4; kk++) {
            unsigned af[2][4];
#pragma unroll
            for (int mf = 0; mf < 2; mf++) {
                const int row = mf * 16 + r4;
                const int k = kk * 8 + c4;
                af[mf][0] = __float_as_uint(Ps[row * APSTR + k]);
                af[mf][1] = __float_as_uint(Ps[(row + 8) * APSTR + k]);
                af[mf][2] = __float_as_uint(Ps[row * APSTR + k + 4]);
                af[mf][3] = __float_as_uint(Ps[(row + 8) * APSTR + k + 4]);
            }
#pragma unroll
            for (int j = 0; j < 8; j++) {
                const int key = kk * 8 + c4;
                const int d = j * 8 + r4;
                const unsigned b0 = __float_as_uint(sm[AOFF_V + key * AVSTR + d]);
                const unsigned b1 = __float_as_uint(sm[AOFF_V + (key + 4) * AVSTR + d]);
                mma_tf32(oacc[0][j], af[0], b0, b1);
                mma_tf32(oacc[1][j], af[1], b0, b1);
            }
        }
        __syncthreads();
    }

    // ---- epilogue ----
#pragma unroll
    for (int mf = 0; mf < 2; mf++) {
        const float invA = 1.f / lrow[mf][0];
        const float invB = 1.f / lrow[mf][1];
        const size_t t = (size_t)b * SEQ + q0 + warp * 32 + mf * 16 + r4;
        float* ob = g_att + t * D_MODEL + h * HD;
#pragma unroll
        for (int j = 0; j < 8; j++) {
            const int cc = j * 8 + 2 * c4;
            *(float2*)&ob[cc] =
                make_float2(oacc[mf][j][0] * invA, oacc[mf][j][1] * invA);
            *(float2*)&ob[8 * D_MODEL + cc] =
                make_float2(oacc[mf][j][2] * invB, oacc[mf][j][3] * invB);
        }
    }
}

// ---------------------------------------------------------------------------
extern "C" void kernel_launch(void* const* d_in, const int* in_sizes, int n_in,
                              void* d_out, int out_size)
{
    const float* x    = (const float*)d_in[0];
    const float* Wqkv = (const float*)d_in[1];
    const float* bqkv = (const float*)d_in[2];
    const float* Wout = (const float*)d_in[3];
    const float* bout = (const float*)d_in[4];
    float* out = (float*)d_out;

    float *qkvbuf = nullptr, *attbuf = nullptr, *wqkvF = nullptr, *woutF = nullptr;
    cudaGetSymbolAddress((void**)&qkvbuf, g_qkv);
    cudaGetSymbolAddress((void**)&attbuf, g_att);
    cudaGetSymbolAddress((void**)&wqkvF, g_wqkvF);
    cudaGetSymbolAddress((void**)&woutF, g_woutF);

    cudaFuncSetAttribute(attn_mma_v2_kernel,
                         cudaFuncAttributeMaxDynamicSharedMemorySize, ATT_SMEM_BYTES);

    // 0) permute weights into fragment order (tf32)
    {
        const int t1 = (QKV_LD / 64) * (D_MODEL / 8) * 8 * 32;
        permute_w_kernel<<<(t1 + 255) / 256, 256>>>(Wqkv, wqkvF, D_MODEL, QKV_LD);
        const int t2 = (D_MODEL / 64) * (D_MODEL / 8) * 8 * 32;
        permute_w_kernel<<<(t2 + 255) / 256, 256>>>(Wout, woutF, D_MODEL, D_MODEL);
    }
    // 1) qkv = x @ Wqkv + bqkv  [4096, 3072]
    {
        dim3 grid(QKV_LD / 128, NTOK / 128);   // (24, 32)
        gemm_v2_kernel<<<grid, 128>>>(x, wqkvF, bqkv, qkvbuf, NTOK, QKV_LD, D_MODEL);
    }
    // 2) attention
    {
        dim3 grid(SEQ / 256, NHEAD, BATCH);    // (8, 16, 2)
        attn_mma_v2_kernel<<<grid, 256, ATT_SMEM_BYTES>>>();
    }
    // 3) out = att @ Wout + bout  [4096, 1024]
    {
        dim3 grid(D_MODEL / 128, NTOK / 128);  // (8, 32)
        gemm_v2_kernel<<<grid, 128>>>(attbuf, woutF, bout, out, NTOK, D_MODEL, D_MODEL);
    }
}

// round 5
// speedup vs baseline: 1.4252x; 1.4252x over previous
#include <cuda_runtime.h>
#include <math.h>
#include <stdint.h>

// Problem constants
#define D_MODEL 1024
#define NHEAD   16
#define HD      64
#define SEQ     2048
#define BATCH   2
#define NTOK    (BATCH * SEQ)          // 4096
#define QKV_LD  (3 * D_MODEL)          // 3072

// HBM scratch (no cudaMalloc allowed)
__device__ float g_qkv[(size_t)NTOK * QKV_LD];        // [4096, 3072]
__device__ float g_att[(size_t)NTOK * D_MODEL];       // [4096, 1024] (tf32-rounded)
__device__ float g_xtf[(size_t)NTOK * D_MODEL];       // x, tf32-rounded
__device__ float g_wqkv_tf[(size_t)D_MODEL * QKV_LD]; // Wqkv, tf32-rounded
__device__ float g_wout_tf[(size_t)D_MODEL * D_MODEL];// Wout, tf32-rounded

// ---------------------------------------------------------------------------
__device__ __forceinline__ unsigned f2tf(float f) {
    unsigned u;
    asm("cvt.rna.tf32.f32 %0, %1;" : "=r"(u) : "f"(f));
    return u;
}
__device__ __forceinline__ float f2tf_f(float f) { return __uint_as_float(f2tf(f)); }

__device__ __forceinline__ uint32_t smem_u32(const void* p) {
    uint32_t a;
    asm("{ .reg .u64 t; cvta.to.shared.u64 t, %1; cvt.u32.u64 %0, t; }"
        : "=r"(a) : "l"(p));
    return a;
}

__device__ __forceinline__ void mma_tf32(float c[4], const unsigned a[4],
                                         unsigned b0, unsigned b1) {
    asm volatile(
        "mma.sync.aligned.m16n8k8.row.col.f32.tf32.tf32.f32 "
        "{%0,%1,%2,%3}, {%4,%5,%6,%7}, {%8,%9}, {%0,%1,%2,%3};"
        : "+f"(c[0]), "+f"(c[1]), "+f"(c[2]), "+f"(c[3])
        : "r"(a[0]), "r"(a[1]), "r"(a[2]), "r"(a[3]), "r"(b0), "r"(b1));
}

#define CP16(dst, src) \
    asm volatile("cp.async.cg.shared.global [%0], [%1], 16;" \
                 :: "r"(dst), "l"(src) : "memory")
#define CP_COMMIT() asm volatile("cp.async.commit_group;" ::: "memory")
#define CP_WAIT(n)  asm volatile("cp.async.wait_group %0;" :: "n"(n) : "memory")

// ---------------------------------------------------------------------------
// tf32 rounding pre-pass (vectorized copy)
// ---------------------------------------------------------------------------
__global__ __launch_bounds__(256) void cvt_tf32_kernel(
    const float4* __restrict__ src, float4* __restrict__ dst, int n4)
{
    for (int i = blockIdx.x * 256 + threadIdx.x; i < n4; i += gridDim.x * 256) {
        float4 v = src[i];
        dst[i] = make_float4(f2tf_f(v.x), f2tf_f(v.y), f2tf_f(v.z), f2tf_f(v.w));
    }
}

// ---------------------------------------------------------------------------
// TF32 mma.sync GEMM v3: C[M,N] = A[M,K] @ B[K,N] + bias[N]
// Operands pre-rounded to tf32 in gmem. cp.async 4-stage pipeline.
// CTA 128x128, 4 warps (2x2 of 64x64), 2 CTAs/SM.
// As [m][k] stride 20 floats; Bs [k][n] stride 136 floats (both conflict-free).
// ---------------------------------------------------------------------------
#define ASTR 20
#define BSTR 136
#define A_ST_FLOATS (128 * ASTR)                 // 2560
#define B_ST_FLOATS (16 * BSTR)                  // 2176
#define STAGE_FLOATS (A_ST_FLOATS + B_ST_FLOATS) // 4736
#define GEMM_SMEM_BYTES (4 * STAGE_FLOATS * 4)   // 75776

__global__ __launch_bounds__(128, 2) void gemm_v3_kernel(
    const float* __restrict__ A, const float* __restrict__ B,
    const float* __restrict__ bias, float* __restrict__ C,
    int M, int N, int K)
{
    extern __shared__ float sm[];
    const uint32_t smb = smem_u32(sm);

    const int tid  = threadIdx.x;
    const int lane = tid & 31;
    const int warp = tid >> 5;
    const int r4 = lane >> 2;
    const int c4 = lane & 3;
    const int wrow = (warp >> 1) * 64;
    const int wcol = (warp & 1) * 64;
    const int row0 = blockIdx.y * 128;
    const int col0 = blockIdx.x * 128;

    const float* Ablk = A + (size_t)row0 * K;
    const float* Bblk = B + col0;

    const int nchunk = K / 16;

#define GEMM_STAGE(c, st) do {                                               \
        const float* Ag = Ablk + (c) * 16;                                   \
        _Pragma("unroll")                                                    \
        for (int i = 0; i < 4; i++) {                                        \
            const int id = tid + 128 * i;                                    \
            const int r = id >> 2, ks = id & 3;                              \
            CP16(smb + (uint32_t)(((st) * STAGE_FLOATS + r * ASTR + ks * 4) * 4), \
                 Ag + (size_t)r * K + ks * 4);                               \
        }                                                                    \
        const float* Bg = Bblk + (size_t)((c) * 16) * N;                     \
        _Pragma("unroll")                                                    \
        for (int i = 0; i < 4; i++) {                                        \
            const int id = tid + 128 * i;                                    \
            const int kk = id >> 5, ns = id & 31;                            \
            CP16(smb + (uint32_t)(((st) * STAGE_FLOATS + A_ST_FLOATS + kk * BSTR + ns * 4) * 4), \
                 Bg + (size_t)kk * N + ns * 4);                              \
        }                                                                    \
        CP_COMMIT();                                                         \
    } while (0)

    float acc[4][8][4];
#pragma unroll
    for (int mf = 0; mf < 4; mf++)
#pragma unroll
        for (int nf = 0; nf < 8; nf++)
#pragma unroll
            for (int x = 0; x < 4; x++) acc[mf][nf][x] = 0.f;

    // prologue: 3 stages in flight
    GEMM_STAGE(0, 0);
    GEMM_STAGE(1, 1);
    GEMM_STAGE(2, 2);

    for (int c = 0; c < nchunk; c++) {
        CP_WAIT(2);
        __syncthreads();

        const float* As_ = sm + (c & 3) * STAGE_FLOATS;
        const float* Bs_ = As_ + A_ST_FLOATS;

#pragma unroll
        for (int ks = 0; ks < 2; ks++) {
            const int k = ks * 8 + c4;
            unsigned af[4][4];
#pragma unroll
            for (int mf = 0; mf < 4; mf++) {
                const int m = wrow + mf * 16 + r4;
                af[mf][0] = __float_as_uint(As_[m * ASTR + k]);
                af[mf][1] = __float_as_uint(As_[(m + 8) * ASTR + k]);
                af[mf][2] = __float_as_uint(As_[m * ASTR + k + 4]);
                af[mf][3] = __float_as_uint(As_[(m + 8) * ASTR + k + 4]);
            }
            unsigned bf0[8], bf1[8];
#pragma unroll
            for (int nf = 0; nf < 8; nf++) {
                const int n = wcol + nf * 8 + r4;
                bf0[nf] = __float_as_uint(Bs_[k * BSTR + n]);
                bf1[nf] = __float_as_uint(Bs_[(k + 4) * BSTR + n]);
            }
#pragma unroll
            for (int nf = 0; nf < 8; nf++)
#pragma unroll
                for (int mf = 0; mf < 4; mf++)
                    mma_tf32(acc[mf][nf], af[mf], bf0[nf], bf1[nf]);
        }

        if (c + 3 < nchunk) { GEMM_STAGE(c + 3, (c + 3) & 3); }
        else { CP_COMMIT(); }   // keep group count constant for CP_WAIT(2)
    }

    // epilogue
#pragma unroll
    for (int mf = 0; mf < 4; mf++) {
        const int r = row0 + wrow + mf * 16 + r4;
#pragma unroll
        for (int nf = 0; nf < 8; nf++) {
            const int cc = col0 + wcol + nf * 8 + 2 * c4;
            const float bx = bias[cc], by = bias[cc + 1];
            *(float2*)&C[(size_t)r * N + cc] =
                make_float2(acc[mf][nf][0] + bx, acc[mf][nf][1] + by);
            *(float2*)&C[(size_t)(r + 8) * N + cc] =
                make_float2(acc[mf][nf][2] + bx, acc[mf][nf][3] + by);
        }
    }
#undef GEMM_STAGE
}

// ---------------------------------------------------------------------------
// FlashAttention tf32 mma v3: R1 structure + cp.async double-buffered K/V.
// 8 warps x 16 q-rows = 128 q / CTA. K/V copied raw fp32 (mma truncates to
// tf32); Q scaled+rounded once; P rounded at store.
// smem floats: KV buf0 K[64][68],V[64][72]; buf1 same; P 8*[16][68].
// Q staging overlays the KV region before the pipeline starts.
// ---------------------------------------------------------------------------
#define AKSTR 68
#define AVSTR 72
#define APSTR 68
#define KOFF0 0
#define VOFF0 (64 * AKSTR)                    // 4352
#define KOFF1 (VOFF0 + 64 * AVSTR)            // 8960
#define VOFF1 (KOFF1 + 64 * AKSTR)            // 13312
#define POFF  (VOFF1 + 64 * AVSTR)            // 17920
#define ATT_SMEM_FLOATS (POFF + 8 * 16 * APSTR)  // 26624
#define ATT_SMEM_BYTES  (ATT_SMEM_FLOATS * 4)    // 106496

__global__ __launch_bounds__(256) void attn_v3_kernel()
{
    extern __shared__ float sm[];
    const uint32_t smb = smem_u32(sm);
    const int tid  = threadIdx.x;
    const int lane = tid & 31;
    const int warp = tid >> 5;
    const int b  = blockIdx.z;
    const int h  = blockIdx.y;
    const int q0 = blockIdx.x * 128;
    const int r4 = lane >> 2;
    const int c4 = lane & 3;

    float* Ps = sm + POFF + warp * (16 * APSTR);
    const int koff[2] = {KOFF0, KOFF1};
    const int voff[2] = {VOFF0, VOFF1};

    // ---- Stage Q (scaled, tf32) into sm[128][68], extract frags ----
    {
        const float* qb = g_qkv + ((size_t)b * SEQ + q0) * QKV_LD + h * (3 * HD);
        for (int i = tid; i < 128 * 16; i += 256) {
            const int r = i >> 4;
            const int cc = (i & 15) * 4;
            float4 v = *(const float4*)(qb + (size_t)r * QKV_LD + cc);
            sm[r * AKSTR + cc + 0] = f2tf_f(v.x * 0.125f);
            sm[r * AKSTR + cc + 1] = f2tf_f(v.y * 0.125f);
            sm[r * AKSTR + cc + 2] = f2tf_f(v.z * 0.125f);
            sm[r * AKSTR + cc + 3] = f2tf_f(v.w * 0.125f);
        }
    }
    __syncthreads();

    unsigned qf[8][4];
    {
        const int m = warp * 16 + r4;
#pragma unroll
        for (int kk = 0; kk < 8; kk++) {
            const int k = kk * 8 + c4;
            qf[kk][0] = __float_as_uint(sm[m * AKSTR + k]);
            qf[kk][1] = __float_as_uint(sm[(m + 8) * AKSTR + k]);
            qf[kk][2] = __float_as_uint(sm[m * AKSTR + k + 4]);
            qf[kk][3] = __float_as_uint(sm[(m + 8) * AKSTR + k + 4]);
        }
    }
    __syncthreads();   // Q area about to be overwritten by K/V pipeline

    const float* kvhead = g_qkv + (size_t)b * SEQ * QKV_LD + h * (3 * HD) + HD;

#define ATT_STAGE(t, bufi) do {                                              \
        const float* kvb = kvhead + (size_t)(t) * 64 * QKV_LD;               \
        _Pragma("unroll")                                                    \
        for (int i = 0; i < 8; i++) {                                        \
            const int id = tid + 256 * i;                                    \
            const int r = id >> 5;                                           \
            const int s = id & 31;                                           \
            const float* src = kvb + (size_t)r * QKV_LD +                    \
                               (s < 16 ? s * 4 : 64 + (s - 16) * 4);         \
            const uint32_t dst = smb + (uint32_t)((s < 16                    \
                ? koff[bufi] + r * AKSTR + s * 4                             \
                : voff[bufi] + r * AVSTR + (s - 16) * 4) * 4);               \
            CP16(dst, src);                                                  \
        }                                                                    \
        CP_COMMIT();                                                         \
    } while (0)

    float oacc[8][4];
#pragma unroll
    for (int j = 0; j < 8; j++)
#pragma unroll
        for (int x = 0; x < 4; x++) oacc[j][x] = 0.f;
    float mrow[2] = {-INFINITY, -INFINITY};
    float lrow[2] = {0.f, 0.f};

    const int ntile = SEQ / 64;   // 32
    ATT_STAGE(0, 0);

    for (int t = 0; t < ntile; t++) {
        const int bi = t & 1;
        if (t + 1 < ntile) { ATT_STAGE(t + 1, (t + 1) & 1); }
        else { CP_COMMIT(); }
        CP_WAIT(1);
        __syncthreads();

        const float* Ks = sm + koff[bi];
        const float* Vs = sm + voff[bi];

        // ---- S = Q @ K^T ----
        float sacc[8][4];
#pragma unroll
        for (int j = 0; j < 8; j++) {
            sacc[j][0] = sacc[j][1] = sacc[j][2] = sacc[j][3] = 0.f;
#pragma unroll
            for (int kk = 0; kk < 8; kk++) {
                const int key = j * 8 + r4;
                const int d = kk * 8 + c4;
                const unsigned b0 = __float_as_uint(Ks[key * AKSTR + d]);
                const unsigned b1 = __float_as_uint(Ks[key * AKSTR + d + 4]);
                mma_tf32(sacc[j], qf[kk], b0, b1);
            }
        }

        // ---- online softmax ----
        float mA = sacc[0][0], mB = sacc[0][2];
#pragma unroll
        for (int j = 0; j < 8; j++) {
            mA = fmaxf(mA, fmaxf(sacc[j][0], sacc[j][1]));
            mB = fmaxf(mB, fmaxf(sacc[j][2], sacc[j][3]));
        }
        mA = fmaxf(mA, __shfl_xor_sync(0xffffffffu, mA, 1));
        mA = fmaxf(mA, __shfl_xor_sync(0xffffffffu, mA, 2));
        mB = fmaxf(mB, __shfl_xor_sync(0xffffffffu, mB, 1));
        mB = fmaxf(mB, __shfl_xor_sync(0xffffffffu, mB, 2));
        const float mnA = fmaxf(mrow[0], mA);
        const float mnB = fmaxf(mrow[1], mB);
        const float alA = __expf(mrow[0] - mnA);
        const float alB = __expf(mrow[1] - mnB);
        mrow[0] = mnA; mrow[1] = mnB;

        float sumA = 0.f, sumB = 0.f;
#pragma unroll
        for (int j = 0; j < 8; j++) {
            const float p0 = __expf(sacc[j][0] - mnA);
            const float p1 = __expf(sacc[j][1] - mnA);
            const float p2 = __expf(sacc[j][2] - mnB);
            const float p3 = __expf(sacc[j][3] - mnB);
            sumA += p0 + p1;
            sumB += p2 + p3;
            const int cc = j * 8 + 2 * c4;
            Ps[r4 * APSTR + cc]           = f2tf_f(p0);
            Ps[r4 * APSTR + cc + 1]       = f2tf_f(p1);
            Ps[(r4 + 8) * APSTR + cc]     = f2tf_f(p2);
            Ps[(r4 + 8) * APSTR + cc + 1] = f2tf_f(p3);
        }
        sumA += __shfl_xor_sync(0xffffffffu, sumA, 1);
        sumA += __shfl_xor_sync(0xffffffffu, sumA, 2);
        sumB += __shfl_xor_sync(0xffffffffu, sumB, 1);
        sumB += __shfl_xor_sync(0xffffffffu, sumB, 2);
        lrow[0] = lrow[0] * alA + sumA;
        lrow[1] = lrow[1] * alB + sumB;

#pragma unroll
        for (int j = 0; j < 8; j++) {
            oacc[j][0] *= alA; oacc[j][1] *= alA;
            oacc[j][2] *= alB; oacc[j][3] *= alB;
        }
        __syncwarp();

        // ---- O += P @ V ----
#pragma unroll
        for (int kk = 0; kk < 8; kk++) {
            unsigned af[4];
            const int k = kk * 8 + c4;
            af[0] = __float_as_uint(Ps[r4 * APSTR + k]);
            af[1] = __float_as_uint(Ps[(r4 + 8) * APSTR + k]);
            af[2] = __float_as_uint(Ps[r4 * APSTR + k + 4]);
            af[3] = __float_as_uint(Ps[(r4 + 8) * APSTR + k + 4]);
#pragma unroll
            for (int j = 0; j < 8; j++) {
                const int key = kk * 8 + c4;
                const int d = j * 8 + r4;
                const unsigned b0 = __float_as_uint(Vs[key * AVSTR + d]);
                const unsigned b1 = __float_as_uint(Vs[(key + 4) * AVSTR + d]);
                mma_tf32(oacc[j], af, b0, b1);
            }
        }
        __syncthreads();
    }

    // ---- epilogue: O /= l, tf32-round, store ----
    const float invA = 1.f / lrow[0];
    const float invB = 1.f / lrow[1];
    const size_t t = (size_t)b * SEQ + q0 + warp * 16 + r4;
    float* ob = g_att + t * D_MODEL + h * HD;
#pragma unroll
    for (int j = 0; j < 8; j++) {
        const int cc = j * 8 + 2 * c4;
        *(float2*)&ob[cc] = make_float2(f2tf_f(oacc[j][0] * invA),
                                        f2tf_f(oacc[j][1] * invA));
        *(float2*)&ob[8 * D_MODEL + cc] = make_float2(f2tf_f(oacc[j][2] * invB),
                                                      f2tf_f(oacc[j][3] * invB));
    }
#undef ATT_STAGE
}

// ---------------------------------------------------------------------------
extern "C" void kernel_launch(void* const* d_in, const int* in_sizes, int n_in,
                              void* d_out, int out_size)
{
    const float* x    = (const float*)d_in[0];
    const float* Wqkv = (const float*)d_in[1];
    const float* bqkv = (const float*)d_in[2];
    const float* Wout = (const float*)d_in[3];
    const float* bout = (const float*)d_in[4];
    float* out = (float*)d_out;

    float *qkvbuf, *attbuf, *xtf, *wqkvtf, *wouttf;
    cudaGetSymbolAddress((void**)&qkvbuf, g_qkv);
    cudaGetSymbolAddress((void**)&attbuf, g_att);
    cudaGetSymbolAddress((void**)&xtf, g_xtf);
    cudaGetSymbolAddress((void**)&wqkvtf, g_wqkv_tf);
    cudaGetSymbolAddress((void**)&wouttf, g_wout_tf);

    cudaFuncSetAttribute(gemm_v3_kernel,
                         cudaFuncAttributeMaxDynamicSharedMemorySize, GEMM_SMEM_BYTES);
    cudaFuncSetAttribute(attn_v3_kernel,
                         cudaFuncAttributeMaxDynamicSharedMemorySize, ATT_SMEM_BYTES);

    // 0) tf32 rounding pre-passes
    cvt_tf32_kernel<<<592, 256>>>((const float4*)x, (float4*)xtf,
                                  NTOK * D_MODEL / 4);
    cvt_tf32_kernel<<<592, 256>>>((const float4*)Wqkv, (float4*)wqkvtf,
                                  D_MODEL * QKV_LD / 4);
    cvt_tf32_kernel<<<592, 256>>>((const float4*)Wout, (float4*)wouttf,
                                  D_MODEL * D_MODEL / 4);

    // 1) qkv = x @ Wqkv + bqkv  [4096, 3072]
    {
        dim3 grid(QKV_LD / 128, NTOK / 128);   // (24, 32)
        gemm_v3_kernel<<<grid, 128, GEMM_SMEM_BYTES>>>(
            xtf, wqkvtf, bqkv, qkvbuf, NTOK, QKV_LD, D_MODEL);
    }
    // 2) attention
    {
        dim3 grid(SEQ / 128, NHEAD, BATCH);    // (16, 16, 2)
        attn_v3_kernel<<<grid, 256, ATT_SMEM_BYTES>>>();
    }
    // 3) out = att @ Wout + bout  [4096, 1024]
    {
        dim3 grid(D_MODEL / 128, NTOK / 128);  // (8, 32)
        gemm_v3_kernel<<<grid, 128, GEMM_SMEM_BYTES>>>(
            attbuf, wouttf, bout, out, NTOK, D_MODEL, D_MODEL);
    }
}

// round 7
// speedup vs baseline: 2.8653x; 2.0104x over previous
#include <cuda_runtime.h>
#include <cuda_fp16.h>
#include <math.h>
#include <stdint.h>

// Problem constants
#define D_MODEL 1024
#define NHEAD   16
#define HD      64
#define SEQ     2048
#define BATCH   2
#define NTOK    (BATCH * SEQ)          // 4096
#define QKV_LD  (3 * D_MODEL)          // 3072

// HBM scratch (no cudaMalloc allowed)
__device__ __half g_xh[(size_t)NTOK * D_MODEL];        // x fp16
__device__ __half g_wqkvTh[(size_t)QKV_LD * D_MODEL];  // Wqkv^T fp16 [3072][1024]
__device__ __half g_woutTh[(size_t)D_MODEL * D_MODEL]; // Wout^T fp16 [1024][1024]
__device__ __half g_qkvh[(size_t)NTOK * QKV_LD];       // Q(scaled)/K fp16 (V region unused)
__device__ __half g_vt[(size_t)BATCH * NHEAD * HD * SEQ]; // V^T fp16 [bh][d][s]
__device__ __half g_atth[(size_t)NTOK * D_MODEL];      // attention out fp16

// ---------------------------------------------------------------------------
__device__ __forceinline__ uint32_t smem_u32(const void* p) {
    uint32_t a;
    asm("{ .reg .u64 t; cvta.to.shared.u64 t, %1; cvt.u32.u64 %0, t; }"
        : "=r"(a) : "l"(p));
    return a;
}
__device__ __forceinline__ unsigned h2_to_u32(__half2 h) {
    return *reinterpret_cast<unsigned*>(&h);
}
__device__ __forceinline__ void mma_f16(float c[4], const unsigned a[4],
                                        unsigned b0, unsigned b1) {
    asm volatile(
        "mma.sync.aligned.m16n8k16.row.col.f32.f16.f16.f32 "
        "{%0,%1,%2,%3}, {%4,%5,%6,%7}, {%8,%9}, {%0,%1,%2,%3};"
        : "+f"(c[0]), "+f"(c[1]), "+f"(c[2]), "+f"(c[3])
        : "r"(a[0]), "r"(a[1]), "r"(a[2]), "r"(a[3]), "r"(b0), "r"(b1));
}
#define CP16(dst, src) \
    asm volatile("cp.async.cg.shared.global [%0], [%1], 16;" \
                 :: "r"(dst), "l"(src) : "memory")
#define CP_COMMIT() asm volatile("cp.async.commit_group;" ::: "memory")
#define CP_WAIT(n)  asm volatile("cp.async.wait_group %0;" :: "n"(n) : "memory")

// ---------------------------------------------------------------------------
// Pre-passes: fp32 -> fp16 copy; fp32 transpose -> fp16
// ---------------------------------------------------------------------------
__global__ __launch_bounds__(256) void cvt_h_kernel(
    const float4* __restrict__ src, uint4* __restrict__ dst, int n8)
{
    for (int i = blockIdx.x * 256 + threadIdx.x; i < n8; i += gridDim.x * 256) {
        float4 a = src[2 * i], b = src[2 * i + 1];
        uint4 o;
        o.x = h2_to_u32(__floats2half2_rn(a.x, a.y));
        o.y = h2_to_u32(__floats2half2_rn(a.z, a.w));
        o.z = h2_to_u32(__floats2half2_rn(b.x, b.y));
        o.w = h2_to_u32(__floats2half2_rn(b.z, b.w));
        dst[i] = o;
    }
}

__global__ void transpose_cvt_kernel(
    const float* __restrict__ in, __half* __restrict__ out, int R, int C)
{
    __shared__ float t[32][33];
    const int bx = blockIdx.x * 32;   // col base
    const int by = blockIdx.y * 32;   // row base
    const int x = threadIdx.x, y = threadIdx.y;
#pragma unroll
    for (int j = 0; j < 32; j += 8)
        t[y + j][x] = in[(size_t)(by + y + j) * C + bx + x];
    __syncthreads();
#pragma unroll
    for (int j = 0; j < 32; j += 8)
        out[(size_t)(bx + y + j) * R + by + x] = __float2half(t[x][y + j]);
}

// ---------------------------------------------------------------------------
// FP16 mma.sync GEMM: C[M,N] = A[M,K] @ Bt[N,K]^T + bias[N]
// CTA 128x128, 4 warps (2x2 of 64x64), cp.async 4-stage, K-chunk 32.
// As [m][k] and Bs [n][k] fp16, row stride 40 half (20 words -> bank-bijective
// LDS.32 fragment loads).
// mode 0: fp32 out.  mode 1: qkv special (Q scaled fp16, K fp16, V -> g_vt).
// ---------------------------------------------------------------------------
#define HSTR 40
#define A_ST_H (128 * HSTR)              // 5120 half
#define STG_H  (2 * A_ST_H)              // 10240 half per stage (A + B)
#define GEMM_SMEM_BYTES (4 * STG_H * 2)  // 81920

__global__ __launch_bounds__(128, 2) void gemm_h_kernel(
    const __half* __restrict__ A, const __half* __restrict__ Bt,
    const float* __restrict__ bias, void* __restrict__ Cout,
    int M, int N, int K, int mode)
{
    extern __shared__ __half smh[];
    const uint32_t smb = smem_u32(smh);

    const int tid  = threadIdx.x;
    const int lane = tid & 31;
    const int warp = tid >> 5;
    const int r4 = lane >> 2;
    const int c4 = lane & 3;
    const int wrow = (warp >> 1) * 64;
    const int wcol = (warp & 1) * 64;
    const int row0 = blockIdx.y * 128;
    const int col0 = blockIdx.x * 128;

    const __half* Ablk = A  + (size_t)row0 * K;
    const __half* Bblk = Bt + (size_t)col0 * K;

#define GSTAGE(c, st) do {                                                   \
        const __half* Ag = Ablk + (c) * 32;                                  \
        const __half* Bg = Bblk + (c) * 32;                                  \
        _Pragma("unroll")                                                    \
        for (int i = 0; i < 4; i++) {                                        \
            const int id = tid + 128 * i;                                    \
            const int r = id >> 2, ch = id & 3;                              \
            CP16(smb + (uint32_t)(((st) * STG_H + r * HSTR + ch * 8) * 2),   \
                 Ag + (size_t)r * K + ch * 8);                               \
            CP16(smb + (uint32_t)(((st) * STG_H + A_ST_H + r * HSTR + ch * 8) * 2), \
                 Bg + (size_t)r * K + ch * 8);                               \
        }                                                                    \
        CP_COMMIT();                                                         \
    } while (0)

    float acc[4][8][4];
#pragma unroll
    for (int mf = 0; mf < 4; mf++)
#pragma unroll
        for (int nf = 0; nf < 8; nf++)
#pragma unroll
            for (int x = 0; x < 4; x++) acc[mf][nf][x] = 0.f;

    const int nchunk = K / 32;
    GSTAGE(0, 0);
    GSTAGE(1, 1);
    GSTAGE(2, 2);

    for (int c = 0; c < nchunk; c++) {
        CP_WAIT(2);
        __syncthreads();

        const __half* As_ = smh + (c & 3) * STG_H;
        const __half* Bs_ = As_ + A_ST_H;

#pragma unroll
        for (int ks = 0; ks < 2; ks++) {
            const int k0 = ks * 16 + 2 * c4;
            unsigned af[4][4];
#pragma unroll
            for (int mf = 0; mf < 4; mf++) {
                const int m = wrow + mf * 16 + r4;
                af[mf][0] = *(const unsigned*)(As_ + m * HSTR + k0);
                af[mf][1] = *(const unsigned*)(As_ + (m + 8) * HSTR + k0);
                af[mf][2] = *(const unsigned*)(As_ + m * HSTR + k0 + 8);
                af[mf][3] = *(const unsigned*)(As_ + (m + 8) * HSTR + k0 + 8);
            }
            unsigned bf0[8], bf1[8];
#pragma unroll
            for (int nf = 0; nf < 8; nf++) {
                const int n = wcol + nf * 8 + r4;
                bf0[nf] = *(const unsigned*)(Bs_ + n * HSTR + k0);
                bf1[nf] = *(const unsigned*)(Bs_ + n * HSTR + k0 + 8);
            }
#pragma unroll
            for (int nf = 0; nf < 8; nf++)
#pragma unroll
                for (int mf = 0; mf < 4; mf++)
                    mma_f16(acc[mf][nf], af[mf], bf0[nf], bf1[nf]);
        }

        if (c + 3 < nchunk) { GSTAGE(c + 3, (c + 3) & 3); }
        else { CP_COMMIT(); }
    }

    // ---- epilogue ----
    if (mode == 0) {
        float* C = (float*)Cout;
#pragma unroll
        for (int mf = 0; mf < 4; mf++) {
            const int r = row0 + wrow + mf * 16 + r4;
#pragma unroll
            for (int nf = 0; nf < 8; nf++) {
                const int cc = col0 + wcol + nf * 8 + 2 * c4;
                const float bx = bias[cc], by = bias[cc + 1];
                *(float2*)&C[(size_t)r * N + cc] =
                    make_float2(acc[mf][nf][0] + bx, acc[mf][nf][1] + by);
                *(float2*)&C[(size_t)(r + 8) * N + cc] =
                    make_float2(acc[mf][nf][2] + bx, acc[mf][nf][3] + by);
            }
        }
    } else {
        // qkv: section per warp-column block (64-aligned)
        const int cb  = col0 + wcol;
        const int h   = cb / 192;
        const int sec = (cb % 192) / 64;
        if (sec < 2) {
            const float sc = (sec == 0) ? 0.125f : 1.0f;
#pragma unroll
            for (int mf = 0; mf < 4; mf++) {
                const int r = row0 + wrow + mf * 16 + r4;
#pragma unroll
                for (int nf = 0; nf < 8; nf++) {
                    const int cc = cb + nf * 8 + 2 * c4;
                    const float bx = bias[cc], by = bias[cc + 1];
                    __half2 v0 = __floats2half2_rn((acc[mf][nf][0] + bx) * sc,
                                                   (acc[mf][nf][1] + by) * sc);
                    __half2 v1 = __floats2half2_rn((acc[mf][nf][2] + bx) * sc,
                                                   (acc[mf][nf][3] + by) * sc);
                    *(__half2*)&g_qkvh[(size_t)r * QKV_LD + cc] = v0;
                    *(__half2*)&g_qkvh[(size_t)(r + 8) * QKV_LD + cc] = v1;
                }
            }
        } else {
            // V -> g_vt[bh][d][s]
#pragma unroll
            for (int mf = 0; mf < 4; mf++) {
                const int r = row0 + wrow + mf * 16 + r4;
                const int bb = r >> 11, s = r & 2047;
                const int bb8 = (r + 8) >> 11, s8 = (r + 8) & 2047;
#pragma unroll
                for (int nf = 0; nf < 8; nf++) {
                    const int cc = cb + nf * 8 + 2 * c4;
                    const int d = (cc % 192) - 128;
                    const float bx = bias[cc], by = bias[cc + 1];
                    __half* v0 = g_vt + ((size_t)(bb * NHEAD + h) * HD + d) * SEQ;
                    v0[s]        = __float2half(acc[mf][nf][0] + bx);
                    v0[SEQ + s]  = __float2half(acc[mf][nf][1] + by);
                    __half* v8 = g_vt + ((size_t)(bb8 * NHEAD + h) * HD + d) * SEQ;
                    v8[s8]       = __float2half(acc[mf][nf][2] + bx);
                    v8[SEQ + s8] = __float2half(acc[mf][nf][3] + by);
                }
            }
        }
    }
#undef GSTAGE
}

// ---------------------------------------------------------------------------
// FlashAttention fp16 mma: 4 warps x 16 q = 64 queries / CTA, 64-key tiles,
// cp.async double-buffered K and V^T, Q frags direct from gmem (fp16,
// pre-scaled). P stored as half2. Softmax in fp32.
// smem (half): K0[64*72] K1 V0 V1 P[4][16*72]  = 23040 half = 46080 B
// ---------------------------------------------------------------------------
#define TKSTR 72
#define KOFF(bi) ((bi) * 4608)
#define VOFF(bi) (9216 + (bi) * 4608)
#define POFF 18432
#define ATT_SMEM_BYTES (23040 * 2)

__global__ __launch_bounds__(128, 3) void attn_h_kernel()
{
    extern __shared__ __half smh[];
    const uint32_t smb = smem_u32(smh);
    const int tid  = threadIdx.x;
    const int lane = tid & 31;
    const int warp = tid >> 5;
    const int b  = blockIdx.z;
    const int h  = blockIdx.y;
    const int q0 = blockIdx.x * 64;
    const int r4 = lane >> 2;
    const int c4 = lane & 3;

    __half* Ps = smh + POFF + warp * (16 * TKSTR);

    // ---- Q frags direct from gmem (fp16, pre-scaled by GEMM1) ----
    unsigned qf[4][4];
    {
        const __half* qr  = g_qkvh + (size_t)(b * SEQ + q0 + warp * 16 + r4) * QKV_LD + h * 192;
        const __half* qr8 = qr + (size_t)8 * QKV_LD;
#pragma unroll
        for (int kk = 0; kk < 4; kk++) {
            const int k0 = kk * 16 + 2 * c4;
            qf[kk][0] = *(const unsigned*)(qr + k0);
            qf[kk][1] = *(const unsigned*)(qr8 + k0);
            qf[kk][2] = *(const unsigned*)(qr + k0 + 8);
            qf[kk][3] = *(const unsigned*)(qr8 + k0 + 8);
        }
    }

    const __half* Kg = g_qkvh + (size_t)b * SEQ * QKV_LD + h * 192 + 64;
    const __half* Vg = g_vt + (size_t)(b * NHEAD + h) * HD * SEQ;

#define ASTAGE(t, bi) do {                                                   \
        const __half* Kt = Kg + (size_t)(t) * 64 * QKV_LD;                   \
        const __half* Vt = Vg + (t) * 64;                                    \
        _Pragma("unroll")                                                    \
        for (int i = 0; i < 4; i++) {                                        \
            const int id = tid + 128 * i;                                    \
            const int r = id >> 3, ch = id & 7;                              \
            CP16(smb + (uint32_t)((KOFF(bi) + r * TKSTR + ch * 8) * 2),      \
                 Kt + (size_t)r * QKV_LD + ch * 8);                          \
            CP16(smb + (uint32_t)((VOFF(bi) + r * TKSTR + ch * 8) * 2),      \
                 Vt + (size_t)r * SEQ + ch * 8);                             \
        }                                                                    \
        CP_COMMIT();                                                         \
    } while (0)

    float oacc[8][4];
#pragma unroll
    for (int j = 0; j < 8; j++)
#pragma unroll
        for (int x = 0; x < 4; x++) oacc[j][x] = 0.f;
    float mrow[2] = {-INFINITY, -INFINITY};
    float lrow[2] = {0.f, 0.f};

    const int ntile = SEQ / 64;   // 32
    ASTAGE(0, 0);

    for (int t = 0; t < ntile; t++) {
        const int bi = t & 1;
        if (t + 1 < ntile) { ASTAGE(t + 1, bi ^ 1); }
        else { CP_COMMIT(); }
        CP_WAIT(1);
        __syncthreads();

        const __half* Ks = smh + KOFF(bi);
        const __half* Vs = smh + VOFF(bi);

        // ---- S = Q @ K^T ----
        float sacc[8][4];
#pragma unroll
        for (int j = 0; j < 8; j++) {
            sacc[j][0] = sacc[j][1] = sacc[j][2] = sacc[j][3] = 0.f;
            const int key = j * 8 + r4;
#pragma unroll
            for (int kk = 0; kk < 4; kk++) {
                const int k0 = kk * 16 + 2 * c4;
                const unsigned b0 = *(const unsigned*)(Ks + key * TKSTR + k0);
                const unsigned b1 = *(const unsigned*)(Ks + key * TKSTR + k0 + 8);
                mma_f16(sacc[j], qf[kk], b0, b1);
            }
        }

        // ---- online softmax ----
        float mA = sacc[0][0], mB = sacc[0][2];
#pragma unroll
        for (int j = 0; j < 8; j++) {
            mA = fmaxf(mA, fmaxf(sacc[j][0], sacc[j][1]));
            mB = fmaxf(mB, fmaxf(sacc[j][2], sacc[j][3]));
        }
        mA = fmaxf(mA, __shfl_xor_sync(0xffffffffu, mA, 1));
        mA = fmaxf(mA, __shfl_xor_sync(0xffffffffu, mA, 2));
        mB = fmaxf(mB, __shfl_xor_sync(0xffffffffu, mB, 1));
        mB = fmaxf(mB, __shfl_xor_sync(0xffffffffu, mB, 2));
        const float mnA = fmaxf(mrow[0], mA);
        const float mnB = fmaxf(mrow[1], mB);
        const float alA = __expf(mrow[0] - mnA);
        const float alB = __expf(mrow[1] - mnB);
        mrow[0] = mnA; mrow[1] = mnB;

        float sumA = 0.f, sumB = 0.f;
#pragma unroll
        for (int j = 0; j < 8; j++) {
            const float p0 = __expf(sacc[j][0] - mnA);
            const float p1 = __expf(sacc[j][1] - mnA);
            const float p2 = __expf(sacc[j][2] - mnB);
            const float p3 = __expf(sacc[j][3] - mnB);
            sumA += p0 + p1;
            sumB += p2 + p3;
            const int cc = j * 8 + 2 * c4;
            *(__half2*)&Ps[r4 * TKSTR + cc]       = __floats2half2_rn(p0, p1);
            *(__half2*)&Ps[(r4 + 8) * TKSTR + cc] = __floats2half2_rn(p2, p3);
        }
        sumA += __shfl_xor_sync(0xffffffffu, sumA, 1);
        sumA += __shfl_xor_sync(0xffffffffu, sumA, 2);
        sumB += __shfl_xor_sync(0xffffffffu, sumB, 1);
        sumB += __shfl_xor_sync(0xffffffffu, sumB, 2);
        lrow[0] = lrow[0] * alA + sumA;
        lrow[1] = lrow[1] * alB + sumB;

#pragma unroll
        for (int j = 0; j < 8; j++) {
            oacc[j][0] *= alA; oacc[j][1] *= alA;
            oacc[j][2] *= alB; oacc[j][3] *= alB;
        }
        __syncwarp();

        // ---- O += P @ V  (A = P frags, B = Vt frags) ----
#pragma unroll
        for (int kk = 0; kk < 4; kk++) {
            const int k0 = kk * 16 + 2 * c4;
            unsigned af[4];
            af[0] = *(const unsigned*)(Ps + r4 * TKSTR + k0);
            af[1] = *(const unsigned*)(Ps + (r4 + 8) * TKSTR + k0);
            af[2] = *(const unsigned*)(Ps + r4 * TKSTR + k0 + 8);
            af[3] = *(const unsigned*)(Ps + (r4 + 8) * TKSTR + k0 + 8);
#pragma unroll
            for (int j = 0; j < 8; j++) {
                const int d = j * 8 + r4;
                const unsigned b0 = *(const unsigned*)(Vs + d * TKSTR + k0);
                const unsigned b1 = *(const unsigned*)(Vs + d * TKSTR + k0 + 8);
                mma_f16(oacc[j], af, b0, b1);
            }
        }
        __syncthreads();
    }

    // ---- epilogue: O /= l, store fp16 ----
    const float invA = 1.f / lrow[0];
    const float invB = 1.f / lrow[1];
    const size_t tr = (size_t)b * SEQ + q0 + warp * 16 + r4;
    __half* ob = g_atth + tr * D_MODEL + h * HD;
#pragma unroll
    for (int j = 0; j < 8; j++) {
        const int cc = j * 8 + 2 * c4;
        *(__half2*)&ob[cc] = __floats2half2_rn(oacc[j][0] * invA, oacc[j][1] * invA);
        *(__half2*)&ob[8 * D_MODEL + cc] =
            __floats2half2_rn(oacc[j][2] * invB, oacc[j][3] * invB);
    }
#undef ASTAGE
}

// ---------------------------------------------------------------------------
extern "C" void kernel_launch(void* const* d_in, const int* in_sizes, int n_in,
                              void* d_out, int out_size)
{
    const float* x    = (const float*)d_in[0];
    const float* Wqkv = (const float*)d_in[1];
    const float* bqkv = (const float*)d_in[2];
    const float* Wout = (const float*)d_in[3];
    const float* bout = (const float*)d_in[4];
    float* out = (float*)d_out;

    __half *xh, *wqkvTh, *woutTh, *atth;
    cudaGetSymbolAddress((void**)&xh, g_xh);
    cudaGetSymbolAddress((void**)&wqkvTh, g_wqkvTh);
    cudaGetSymbolAddress((void**)&woutTh, g_woutTh);
    cudaGetSymbolAddress((void**)&atth, g_atth);

    cudaFuncSetAttribute(gemm_h_kernel,
                         cudaFuncAttributeMaxDynamicSharedMemorySize, GEMM_SMEM_BYTES);

    // 0) pre-passes: x -> fp16; weights -> transposed fp16
    cvt_h_kernel<<<296, 256>>>((const float4*)x, (uint4*)xh, NTOK * D_MODEL / 8);
    {
        dim3 blk(32, 8);
        transpose_cvt_kernel<<<dim3(QKV_LD / 32, D_MODEL / 32), blk>>>(
            Wqkv, wqkvTh, D_MODEL, QKV_LD);
        transpose_cvt_kernel<<<dim3(D_MODEL / 32, D_MODEL / 32), blk>>>(
            Wout, woutTh, D_MODEL, D_MODEL);
    }
    // 1) qkv = x @ Wqkv + bqkv -> Q(scaled)/K fp16 + V^T fp16
    {
        dim3 grid(QKV_LD / 128, NTOK / 128);   // (24, 32)
        gemm_h_kernel<<<grid, 128, GEMM_SMEM_BYTES>>>(
            xh, wqkvTh, bqkv, nullptr, NTOK, QKV_LD, D_MODEL, 1);
    }
    // 2) attention
    {
        dim3 grid(SEQ / 64, NHEAD, BATCH);     // (32, 16, 2)
        attn_h_kernel<<<grid, 128, ATT_SMEM_BYTES>>>();
    }
    // 3) out = att @ Wout + bout (fp32)
    {
        dim3 grid(D_MODEL / 128, NTOK / 128);  // (8, 32)
        gemm_h_kernel<<<grid, 128, GEMM_SMEM_BYTES>>>(
            atth, woutTh, bout, out, NTOK, D_MODEL, D_MODEL, 0);
    }
}

// round 9
// speedup vs baseline: 3.5589x; 1.2421x over previous
#include <cuda_runtime.h>
#include <cuda_fp16.h>
#include <math.h>
#include <stdint.h>

// Problem constants
#define D_MODEL 1024
#define NHEAD   16
#define HD      64
#define SEQ     2048
#define BATCH   2
#define NTOK    (BATCH * SEQ)          // 4096
#define QKV_LD  (3 * D_MODEL)          // 3072

// Q pre-scale: 1/sqrt(64) * log2(e)  (softmax done base-2)
#define QSCALE 0.18033688011112042f

// HBM scratch (no cudaMalloc allowed)
__device__ __half g_xh[(size_t)NTOK * D_MODEL];
__device__ __half g_wqkvTh[(size_t)QKV_LD * D_MODEL];
__device__ __half g_woutTh[(size_t)D_MODEL * D_MODEL];
__device__ __half g_qkvh[(size_t)NTOK * QKV_LD];          // Q(scaled)/K fp16
__device__ __half g_vt[(size_t)BATCH * NHEAD * HD * SEQ]; // V^T fp16 [bh][d][s]
__device__ __half g_atth[(size_t)NTOK * D_MODEL];

// ---------------------------------------------------------------------------
__device__ __forceinline__ uint32_t smem_u32(const void* p) {
    uint32_t a;
    asm("{ .reg .u64 t; cvta.to.shared.u64 t, %1; cvt.u32.u64 %0, t; }"
        : "=r"(a) : "l"(p));
    return a;
}
__device__ __forceinline__ unsigned h2_to_u32(__half2 h) {
    return *reinterpret_cast<unsigned*>(&h);
}
__device__ __forceinline__ float2 u32_to_f2(unsigned u) {
    __half2 h = *reinterpret_cast<__half2*>(&u);
    return __half22float2(h);
}
__device__ __forceinline__ void mma_f16(float c[4], const unsigned a[4],
                                        unsigned b0, unsigned b1) {
    asm volatile(
        "mma.sync.aligned.m16n8k16.row.col.f32.f16.f16.f32 "
        "{%0,%1,%2,%3}, {%4,%5,%6,%7}, {%8,%9}, {%0,%1,%2,%3};"
        : "+f"(c[0]), "+f"(c[1]), "+f"(c[2]), "+f"(c[3])
        : "r"(a[0]), "r"(a[1]), "r"(a[2]), "r"(a[3]), "r"(b0), "r"(b1));
}
__device__ __forceinline__ void ldsm_x4(unsigned& r0, unsigned& r1,
                                        unsigned& r2, unsigned& r3, uint32_t a) {
    asm volatile("ldmatrix.sync.aligned.m8n8.x4.shared.b16 {%0,%1,%2,%3}, [%4];"
                 : "=r"(r0), "=r"(r1), "=r"(r2), "=r"(r3) : "r"(a));
}
// pack (lo,hi) to f16x2 then 2^x elementwise
__device__ __forceinline__ unsigned ex2_h2(float lo, float hi) {
    unsigned r;
    asm("{\n\t.reg .b32 t;\n\tcvt.rn.f16x2.f32 t, %2, %1;\n\t"
        "ex2.approx.f16x2 %0, t;\n\t}"
        : "=r"(r) : "f"(lo), "f"(hi));
    return r;
}
#define CP16(dst, src) \
    asm volatile("cp.async.cg.shared.global [%0], [%1], 16;" \
                 :: "r"(dst), "l"(src) : "memory")
#define CP_COMMIT() asm volatile("cp.async.commit_group;" ::: "memory")
#define CP_WAIT(n)  asm volatile("cp.async.wait_group %0;" :: "n"(n) : "memory")

// ---------------------------------------------------------------------------
// Pre-passes
// ---------------------------------------------------------------------------
__global__ __launch_bounds__(256) void cvt_h_kernel(
    const float4* __restrict__ src, uint4* __restrict__ dst, int n8)
{
    for (int i = blockIdx.x * 256 + threadIdx.x; i < n8; i += gridDim.x * 256) {
        float4 a = src[2 * i], b = src[2 * i + 1];
        uint4 o;
        o.x = h2_to_u32(__floats2half2_rn(a.x, a.y));
        o.y = h2_to_u32(__floats2half2_rn(a.z, a.w));
        o.z = h2_to_u32(__floats2half2_rn(b.x, b.y));
        o.w = h2_to_u32(__floats2half2_rn(b.z, b.w));
        dst[i] = o;
    }
}

__global__ void transpose_cvt_kernel(
    const float* __restrict__ in, __half* __restrict__ out, int R, int C)
{
    __shared__ float t[32][33];
    const int bx = blockIdx.x * 32;
    const int by = blockIdx.y * 32;
    const int x = threadIdx.x, y = threadIdx.y;
#pragma unroll
    for (int j = 0; j < 32; j += 8)
        t[y + j][x] = in[(size_t)(by + y + j) * C + bx + x];
    __syncthreads();
#pragma unroll
    for (int j = 0; j < 32; j += 8)
        out[(size_t)(bx + y + j) * R + by + x] = __float2half(t[x][y + j]);
}

// ---------------------------------------------------------------------------
// FP16 mma GEMM with LDSM fragment loads.
// CTA 128x128, 4 warps (2x2 of 64x64), cp.async 4-stage, K-chunk 32.
// As [m][k], Bs [n][k], row stride 40 half (LDSM phase-conflict-free).
// mode 0: fp32 out.  mode 1: qkv (Q scaled by QSCALE, K fp16, V -> g_vt).
// ---------------------------------------------------------------------------
#define HSTR 40
#define A_ST_H (128 * HSTR)              // 5120 half
#define STG_H  (2 * A_ST_H)              // 10240 half per stage
#define GEMM_SMEM_BYTES (4 * STG_H * 2)  // 81920

__global__ __launch_bounds__(128, 2) void gemm_h_kernel(
    const __half* __restrict__ A, const __half* __restrict__ Bt,
    const float* __restrict__ bias, void* __restrict__ Cout,
    int M, int N, int K, int mode)
{
    extern __shared__ __half smh[];
    const uint32_t smb = smem_u32(smh);

    const int tid  = threadIdx.x;
    const int lane = tid & 31;
    const int warp = tid >> 5;
    const int r4 = lane >> 2;
    const int c4 = lane & 3;
    const int wrow = (warp >> 1) * 64;
    const int wcol = (warp & 1) * 64;
    const int row0 = blockIdx.y * 128;
    const int col0 = blockIdx.x * 128;

    const __half* Ablk = A  + (size_t)row0 * K;
    const __half* Bblk = Bt + (size_t)col0 * K;

    // LDSM lane offsets (half units)
    const uint32_t loffA = (uint32_t)((lane & 15) * HSTR + (lane >> 4) * 8);
    const uint32_t loffB = (uint32_t)(((lane >> 4) * 8 + (lane & 7)) * HSTR
                                      + ((lane >> 3) & 1) * 8);

#define GSTAGE(c, st) do {                                                   \
        const __half* Ag = Ablk + (c) * 32;                                  \
        const __half* Bg = Bblk + (c) * 32;                                  \
        _Pragma("unroll")                                                    \
        for (int i = 0; i < 4; i++) {                                        \
            const int id = tid + 128 * i;                                    \
            const int r = id >> 2, ch = id & 3;                              \
            CP16(smb + (uint32_t)(((st) * STG_H + r * HSTR + ch * 8) * 2),   \
                 Ag + (size_t)r * K + ch * 8);                               \
            CP16(smb + (uint32_t)(((st) * STG_H + A_ST_H + r * HSTR + ch * 8) * 2), \
                 Bg + (size_t)r * K + ch * 8);                               \
        }                                                                    \
        CP_COMMIT();                                                         \
    } while (0)

    float acc[4][8][4];
#pragma unroll
    for (int mf = 0; mf < 4; mf++)
#pragma unroll
        for (int nf = 0; nf < 8; nf++)
#pragma unroll
            for (int x = 0; x < 4; x++) acc[mf][nf][x] = 0.f;

    const int nchunk = K / 32;
    GSTAGE(0, 0);
    GSTAGE(1, 1);
    GSTAGE(2, 2);

    for (int c = 0; c < nchunk; c++) {
        CP_WAIT(2);
        __syncthreads();

        const uint32_t stA = smb + (uint32_t)(((c & 3) * STG_H) * 2);
        const uint32_t stB = stA + (uint32_t)(A_ST_H * 2);

#pragma unroll
        for (int ks = 0; ks < 2; ks++) {
            unsigned af[4][4];
            const uint32_t aB = stA + (uint32_t)((wrow * HSTR + ks * 16 + loffA) * 2);
#pragma unroll
            for (int mf = 0; mf < 4; mf++)
                ldsm_x4(af[mf][0], af[mf][1], af[mf][2], af[mf][3],
                        aB + (uint32_t)(mf * 16 * HSTR * 2));
            unsigned bf0[8], bf1[8];
            const uint32_t bB = stB + (uint32_t)((wcol * HSTR + ks * 16 + loffB) * 2);
#pragma unroll
            for (int np = 0; np < 4; np++) {
                unsigned r0, r1, r2, r3;
                ldsm_x4(r0, r1, r2, r3, bB + (uint32_t)(np * 16 * HSTR * 2));
                bf0[2 * np] = r0; bf1[2 * np] = r1;
                bf0[2 * np + 1] = r2; bf1[2 * np + 1] = r3;
            }
#pragma unroll
            for (int nf = 0; nf < 8; nf++)
#pragma unroll
                for (int mf = 0; mf < 4; mf++)
                    mma_f16(acc[mf][nf], af[mf], bf0[nf], bf1[nf]);
        }

        if (c + 3 < nchunk) { GSTAGE(c + 3, (c + 3) & 3); }
        else { CP_COMMIT(); }
    }

    // ---- epilogue ----
    if (mode == 0) {
        float* C = (float*)Cout;
#pragma unroll
        for (int mf = 0; mf < 4; mf++) {
            const int r = row0 + wrow + mf * 16 + r4;
#pragma unroll
            for (int nf = 0; nf < 8; nf++) {
                const int cc = col0 + wcol + nf * 8 + 2 * c4;
                const float bx = bias[cc], by = bias[cc + 1];
                *(float2*)&C[(size_t)r * N + cc] =
                    make_float2(acc[mf][nf][0] + bx, acc[mf][nf][1] + by);
                *(float2*)&C[(size_t)(r + 8) * N + cc] =
                    make_float2(acc[mf][nf][2] + bx, acc[mf][nf][3] + by);
            }
        }
    } else {
        const int cb  = col0 + wcol;
        const int h   = cb / 192;
        const int sec = (cb % 192) / 64;
        if (sec < 2) {
            const float sc = (sec == 0) ? QSCALE : 1.0f;
#pragma unroll
            for (int mf = 0; mf < 4; mf++) {
                const int r = row0 + wrow + mf * 16 + r4;
#pragma unroll
                for (int nf = 0; nf < 8; nf++) {
                    const int cc = cb + nf * 8 + 2 * c4;
                    const float bx = bias[cc], by = bias[cc + 1];
                    __half2 v0 = __floats2half2_rn((acc[mf][nf][0] + bx) * sc,
                                                   (acc[mf][nf][1] + by) * sc);
                    __half2 v1 = __floats2half2_rn((acc[mf][nf][2] + bx) * sc,
                                                   (acc[mf][nf][3] + by) * sc);
                    *(__half2*)&g_qkvh[(size_t)r * QKV_LD + cc] = v0;
                    *(__half2*)&g_qkvh[(size_t)(r + 8) * QKV_LD + cc] = v1;
                }
            }
        } else {
#pragma unroll
            for (int mf = 0; mf < 4; mf++) {
                const int r = row0 + wrow + mf * 16 + r4;
                const int bb = r >> 11, s = r & 2047;
                const int bb8 = (r + 8) >> 11, s8 = (r + 8) & 2047;
#pragma unroll
                for (int nf = 0; nf < 8; nf++) {
                    const int cc = cb + nf * 8 + 2 * c4;
                    const int d = (cc % 192) - 128;
                    const float bx = bias[cc], by = bias[cc + 1];
                    __half* v0 = g_vt + ((size_t)(bb * NHEAD + h) * HD + d) * SEQ;
                    v0[s]        = __float2half(acc[mf][nf][0] + bx);
                    v0[SEQ + s]  = __float2half(acc[mf][nf][1] + by);
                    __half* v8 = g_vt + ((size_t)(bb8 * NHEAD + h) * HD + d) * SEQ;
                    v8[s8]       = __float2half(acc[mf][nf][2] + bx);
                    v8[SEQ + s8] = __float2half(acc[mf][nf][3] + by);
                }
            }
        }
    }
#undef GSTAGE
}

// ---------------------------------------------------------------------------
// FlashAttention fp16 mma: P kept in registers (C-frag == A-frag layout),
// base-2 softmax with ex2.approx.f16x2, LDSM for K/V fragments.
// 4 warps x 16 q = 64 q/CTA, 64-key tiles, cp.async double-buffered K & V^T.
// smem (half): K0 K1 V0 V1, each 64*72 = 4608  -> 18432 half = 36864 B
// ---------------------------------------------------------------------------
#define TKSTR 72
#define KOFF(bi) ((bi) * 4608)
#define VOFF(bi) (9216 + (bi) * 4608)
#define ATT_SMEM_BYTES (18432 * 2)

__global__ __launch_bounds__(128, 3) void attn_h_kernel()
{
    extern __shared__ __half smh[];
    const uint32_t smb = smem_u32(smh);
    const int tid  = threadIdx.x;
    const int lane = tid & 31;
    const int warp = tid >> 5;
    const int b  = blockIdx.z;
    const int h  = blockIdx.y;
    const int q0 = blockIdx.x * 64;
    const int r4 = lane >> 2;
    const int c4 = lane & 3;

    // LDSM lane offset for B-operand tiles in [row][k] layout, stride TKSTR
    const uint32_t loffT = (uint32_t)(((lane >> 4) * 8 + (lane & 7)) * TKSTR
                                      + ((lane >> 3) & 1) * 8);

    // ---- Q frags direct from gmem (fp16, pre-scaled by QSCALE) ----
    unsigned qf[4][4];
    {
        const __half* qr  = g_qkvh + (size_t)(b * SEQ + q0 + warp * 16 + r4) * QKV_LD + h * 192;
        const __half* qr8 = qr + (size_t)8 * QKV_LD;
#pragma unroll
        for (int kk = 0; kk < 4; kk++) {
            const int k0 = kk * 16 + 2 * c4;
            qf[kk][0] = *(const unsigned*)(qr + k0);
            qf[kk][1] = *(const unsigned*)(qr8 + k0);
            qf[kk][2] = *(const unsigned*)(qr + k0 + 8);
            qf[kk][3] = *(const unsigned*)(qr8 + k0 + 8);
        }
    }

    const __half* Kg = g_qkvh + (size_t)b * SEQ * QKV_LD + h * 192 + 64;
    const __half* Vg = g_vt + (size_t)(b * NHEAD + h) * HD * SEQ;

#define ASTAGE(t, bi) do {                                                   \
        const __half* Kt = Kg + (size_t)(t) * 64 * QKV_LD;                   \
        const __half* Vt = Vg + (t) * 64;                                    \
        _Pragma("unroll")                                                    \
        for (int i = 0; i < 4; i++) {                                        \
            const int id = tid + 128 * i;                                    \
            const int r = id >> 3, ch = id & 7;                              \
            CP16(smb + (uint32_t)((KOFF(bi) + r * TKSTR + ch * 8) * 2),      \
                 Kt + (size_t)r * QKV_LD + ch * 8);                          \
            CP16(smb + (uint32_t)((VOFF(bi) + r * TKSTR + ch * 8) * 2),      \
                 Vt + (size_t)r * SEQ + ch * 8);                             \
        }                                                                    \
        CP_COMMIT();                                                         \
    } while (0)

    float oacc[8][4];
#pragma unroll
    for (int j = 0; j < 8; j++)
#pragma unroll
        for (int x = 0; x < 4; x++) oacc[j][x] = 0.f;
    float mrow[2] = {-INFINITY, -INFINITY};
    float lrow[2] = {0.f, 0.f};

    const int ntile = SEQ / 64;   // 32
    ASTAGE(0, 0);

    for (int t = 0; t < ntile; t++) {
        const int bi = t & 1;
        if (t + 1 < ntile) { ASTAGE(t + 1, bi ^ 1); }
        else { CP_COMMIT(); }
        CP_WAIT(1);
        __syncthreads();

        const uint32_t ksb = smb + (uint32_t)((KOFF(bi) + loffT) * 2);
        const uint32_t vsb = smb + (uint32_t)((VOFF(bi) + loffT) * 2);

        // ---- S = Q @ K^T  (LDSM for K frags; x4 covers 2 key-groups) ----
        float sacc[8][4];
#pragma unroll
        for (int j = 0; j < 8; j++)
            sacc[j][0] = sacc[j][1] = sacc[j][2] = sacc[j][3] = 0.f;
#pragma unroll
        for (int j2 = 0; j2 < 4; j2++) {
#pragma unroll
            for (int kk = 0; kk < 4; kk++) {
                unsigned b0, b1, b2, b3;
                ldsm_x4(b0, b1, b2, b3,
                        ksb + (uint32_t)((j2 * 16 * TKSTR + kk * 16) * 2));
                mma_f16(sacc[2 * j2],     qf[kk], b0, b1);
                mma_f16(sacc[2 * j2 + 1], qf[kk], b2, b3);
            }
        }

        // ---- online softmax (base-2) ----
        float mA = sacc[0][0], mB = sacc[0][2];
#pragma unroll
        for (int j = 0; j < 8; j++) {
            mA = fmaxf(mA, fmaxf(sacc[j][0], sacc[j][1]));
            mB = fmaxf(mB, fmaxf(sacc[j][2], sacc[j][3]));
        }
        mA = fmaxf(mA, __shfl_xor_sync(0xffffffffu, mA, 1));
        mA = fmaxf(mA, __shfl_xor_sync(0xffffffffu, mA, 2));
        mB = fmaxf(mB, __shfl_xor_sync(0xffffffffu, mB, 1));
        mB = fmaxf(mB, __shfl_xor_sync(0xffffffffu, mB, 2));
        const float mnA = fmaxf(mrow[0], mA);
        const float mnB = fmaxf(mrow[1], mB);
        const float alA = exp2f(mrow[0] - mnA);
        const float alB = exp2f(mrow[1] - mnB);
        mrow[0] = mnA; mrow[1] = mnB;

        // P in registers: pA[j] = half2(p(q,2key),p(q,2key+1)), pB = q+8 rows
        unsigned pA[8], pB[8];
        float sumA = 0.f, sumB = 0.f;
#pragma unroll
        for (int j = 0; j < 8; j++) {
            pA[j] = ex2_h2(sacc[j][0] - mnA, sacc[j][1] - mnA);
            pB[j] = ex2_h2(sacc[j][2] - mnB, sacc[j][3] - mnB);
            float2 fa = u32_to_f2(pA[j]);
            float2 fb = u32_to_f2(pB[j]);
            sumA += fa.x + fa.y;
            sumB += fb.x + fb.y;
        }
        sumA += __shfl_xor_sync(0xffffffffu, sumA, 1);
        sumA += __shfl_xor_sync(0xffffffffu, sumA, 2);
        sumB += __shfl_xor_sync(0xffffffffu, sumB, 1);
        sumB += __shfl_xor_sync(0xffffffffu, sumB, 2);
        lrow[0] = lrow[0] * alA + sumA;
        lrow[1] = lrow[1] * alB + sumB;

#pragma unroll
        for (int j = 0; j < 8; j++) {
            oacc[j][0] *= alA; oacc[j][1] *= alA;
            oacc[j][2] *= alB; oacc[j][3] *= alB;
        }

        // ---- O += P @ V  (P regs are the A frags; LDSM for V frags) ----
#pragma unroll
        for (int d2 = 0; d2 < 4; d2++) {
#pragma unroll
            for (int kk = 0; kk < 4; kk++) {
                unsigned b0, b1, b2, b3;
                ldsm_x4(b0, b1, b2, b3,
                        vsb + (uint32_t)((d2 * 16 * TKSTR + kk * 16) * 2));
                const unsigned af[4] = { pA[2 * kk], pB[2 * kk],
                                         pA[2 * kk + 1], pB[2 * kk + 1] };
                mma_f16(oacc[2 * d2],     af, b0, b1);
                mma_f16(oacc[2 * d2 + 1], af, b2, b3);
            }
        }
        __syncthreads();
    }

    // ---- epilogue: O /= l, store fp16 ----
    const float invA = 1.f / lrow[0];
    const float invB = 1.f / lrow[1];
    const size_t tr = (size_t)b * SEQ + q0 + warp * 16 + r4;
    __half* ob = g_atth + tr * D_MODEL + h * HD;
#pragma unroll
    for (int j = 0; j < 8; j++) {
        const int cc = j * 8 + 2 * c4;
        *(__half2*)&ob[cc] = __floats2half2_rn(oacc[j][0] * invA, oacc[j][1] * invA);
        *(__half2*)&ob[8 * D_MODEL + cc] =
            __floats2half2_rn(oacc[j][2] * invB, oacc[j][3] * invB);
    }
#undef ASTAGE
}

// ---------------------------------------------------------------------------
extern "C" void kernel_launch(void* const* d_in, const int* in_sizes, int n_in,
                              void* d_out, int out_size)
{
    const float* x    = (const float*)d_in[0];
    const float* Wqkv = (const float*)d_in[1];
    const float* bqkv = (const float*)d_in[2];
    const float* Wout = (const float*)d_in[3];
    const float* bout = (const float*)d_in[4];
    float* out = (float*)d_out;

    __half *xh, *wqkvTh, *woutTh, *atth;
    cudaGetSymbolAddress((void**)&xh, g_xh);
    cudaGetSymbolAddress((void**)&wqkvTh, g_wqkvTh);
    cudaGetSymbolAddress((void**)&woutTh, g_woutTh);
    cudaGetSymbolAddress((void**)&atth, g_atth);

    cudaFuncSetAttribute(gemm_h_kernel,
                         cudaFuncAttributeMaxDynamicSharedMemorySize, GEMM_SMEM_BYTES);

    // 0) pre-passes
    cvt_h_kernel<<<296, 256>>>((const float4*)x, (uint4*)xh, NTOK * D_MODEL / 8);
    {
        dim3 blk(32, 8);
        transpose_cvt_kernel<<<dim3(QKV_LD / 32, D_MODEL / 32), blk>>>(
            Wqkv, wqkvTh, D_MODEL, QKV_LD);
        transpose_cvt_kernel<<<dim3(D_MODEL / 32, D_MODEL / 32), blk>>>(
            Wout, woutTh, D_MODEL, D_MODEL);
    }
    // 1) qkv projection
    {
        dim3 grid(QKV_LD / 128, NTOK / 128);   // (24, 32)
        gemm_h_kernel<<<grid, 128, GEMM_SMEM_BYTES>>>(
            xh, wqkvTh, bqkv, nullptr, NTOK, QKV_LD, D_MODEL, 1);
    }
    // 2) attention
    {
        dim3 grid(SEQ / 64, NHEAD, BATCH);     // (32, 16, 2)
        attn_h_kernel<<<grid, 128, ATT_SMEM_BYTES>>>();
    }
    // 3) output projection (fp32)
    {
        dim3 grid(D_MODEL / 128, NTOK / 128);  // (8, 32)
        gemm_h_kernel<<<grid, 128, GEMM_SMEM_BYTES>>>(
            atth, woutTh, bout, out, NTOK, D_MODEL, D_MODEL, 0);
    }
}